// round 11
// baseline (speedup 1.0000x reference)
#include <cuda_runtime.h>
#include <cuda_fp16.h>
#include <cstdint>

// Path_Embedding via mma.sync m16n8k16.f16, single-f16 operands.
// Round 11: B (weight) fragments hoisted into registers for the entire
// persistent loop (64 regs/warp, loaded once) -> B-LDSM eliminated, halving
// steady-state smem traffic. 2 blocks/SM (grid 296), double-buffered E,
// one barrier per tile.

#define VOCAB 100000
#define NPERS 296
#define RSE 160        // e-row stride bytes (+16B nudge when a odd)
#define RSW 144        // w-row stride bytes (+16B nudge when (o>>3)&1)

#define E0_OFF  0      // 160*160 = 25600
#define E1_OFF  25600
#define W_OFF   51200  // 2 taps * 64 * 144 = 18432 (read only during B-hoist)
#define IDX_OFF 69632  // 2*160*4 = 1280
#define RED_OFF 70912  // 2*8*32*4 = 2048
#define SM_TOT  72960

typedef unsigned long long u64;

__device__ __forceinline__ uint32_t smem_u32(const void* p) {
    uint32_t a;
    asm("{ .reg .u64 t; cvta.to.shared.u64 t, %1; cvt.u32.u64 %0, t; }" : "=r"(a) : "l"(p));
    return a;
}

#define LDMX4(r, addr)                                                        \
    asm volatile("ldmatrix.sync.aligned.m8n8.x4.shared.b16 {%0,%1,%2,%3}, [%4];" \
        : "=r"((r)[0]), "=r"((r)[1]), "=r"((r)[2]), "=r"((r)[3]) : "r"(addr))

#define MMA(d, a, b0, b1)                                                     \
    asm volatile("mma.sync.aligned.m16n8k16.row.col.f32.f16.f16.f32 "         \
        "{%0,%1,%2,%3},{%4,%5,%6,%7},{%8,%9},{%0,%1,%2,%3};"                  \
        : "+f"((d)[0]), "+f"((d)[1]), "+f"((d)[2]), "+f"((d)[3])              \
        : "r"((a)[0]), "r"((a)[1]), "r"((a)[2]), "r"((a)[3]),                 \
          "r"(b0), "r"(b1))

__device__ __forceinline__ u64 pack4(float x, float y, float z, float w) {
    __half2 h01 = __float22half2_rn(make_float2(x, y));
    __half2 h23 = __float22half2_rn(make_float2(z, w));
    uint32_t h0 = *reinterpret_cast<uint32_t*>(&h01);
    uint32_t h1 = *reinterpret_cast<uint32_t*>(&h23);
    return (u64)h0 | ((u64)h1 << 32);
}

__global__ __launch_bounds__(256, 2) void path_emb_hmma(
    const int*   __restrict__ path_input,   // [8192,16,5]
    const int*   __restrict__ path_type,    // [5]
    const float* __restrict__ tables,       // [3,100000,64]
    const float* __restrict__ conv_w,       // [64,64,2]
    const float* __restrict__ conv_b,       // [64]
    float*       __restrict__ out)          // [8192,64]
{
    extern __shared__ char smem[];
    const uint32_t sb = smem_u32(smem);
    const int tid  = threadIdx.x;
    const int lane = tid & 31;
    const int wid  = tid >> 5;
    const int mgrp = wid & 3;
    const int ngrp = wid >> 2;

    int (*idx_s)[160]   = reinterpret_cast<int(*)[160]>(smem + IDX_OFF);
    float (*red)[8][32] = reinterpret_cast<float(*)[8][32]>(smem + RED_OFF);
    const float4* tab4  = reinterpret_cast<const float4*>(tables);

    // ---- stage W once per block ----
    {
        const float2* cw2 = reinterpret_cast<const float2*>(conv_w);
        #pragma unroll
        for (int it = 0; it < 16; it++) {
            int i = tid + it * 256;          // i = o*64 + j
            int o = i >> 6, j = i & 63;
            float2 wv = cw2[i];
            int ob = o * RSW + (((o >> 3) & 1) << 4) + j * 2;
            *reinterpret_cast<__half*>(smem + W_OFF + ob)        = __float2half_rn(wv.x);
            *reinterpret_cast<__half*>(smem + W_OFF + 9216 + ob) = __float2half_rn(wv.y);
        }
    }

    // ---- tile-invariant gather addressing: rows k>>3, q-pair k&7 ----
    int      grow[5];
    uint32_t goff[5];
    #pragma unroll
    for (int g = 0; g < 5; g++) {
        int k = tid + g * 256;               // 1280 = 160 rows * 8 q-pairs
        int row = k >> 3, qq = k & 7;
        int a = (row % 80) / 5;
        grow[g] = row;
        goff[g] = (uint32_t)(row * RSE + ((a & 1) << 4) + qq * 16);
    }

    // ---- tile-invariant idx-staging params (tid < 160) ----
    int ib_a = 0, ib_t = 0, ib_b2 = 0, ib_type = 0;
    if (tid < 160) {
        int b2 = tid / 80, rr = tid % 80;
        ib_a = rr / 5; ib_t = rr % 5; ib_b2 = b2;
        ib_type = __ldg(&path_type[ib_t]) * VOCAB;
    }

    // ---- tile-invariant epilogue params (tid < 128) ----
    float bias = 0.f; int ob2 = 0, oc = 0, ow1 = 0, occ_ = 0;
    if (tid < 128) {
        ob2 = tid >> 6; oc = tid & 63;
        ow1 = (oc >> 5) * 4 + ob2 * 2; occ_ = oc & 31;
        bias = __ldg(&conv_b[oc]);
    }

    // ---- ldmatrix lane addresses ----
    uint32_t ab0, ab1, bb0, bb1;
    {
        int m  = mgrp * 32 + (lane & 15);
        int b2 = mgrp >> 1;
        int aa = (m >> 2) & 15, w = m & 3;
        ab0 = (uint32_t)((b2 * 80 + aa * 5 + w) * RSE + ((aa & 1) << 4)
                         + ((lane >> 4) << 4));
        int m1 = m + 16;
        int aa1 = (m1 >> 2) & 15, w1 = m1 & 3;
        ab1 = (uint32_t)((b2 * 80 + aa1 * 5 + w1) * RSE + ((aa1 & 1) << 4)
                         + ((lane >> 4) << 4));
        int nr = ngrp * 32 + (lane & 7) + ((lane >> 4) << 3);
        bb0 = (uint32_t)(nr * RSW + (((nr >> 3) & 1) << 4) + (((lane >> 3) & 1) << 4));
        int nr1 = nr + 16;
        bb1 = (uint32_t)(nr1 * RSW + (((nr1 >> 3) & 1) << 4) + (((lane >> 3) & 1) << 4));
    }
    __syncthreads();   // W staged

    // ---- hoist B fragments into registers ONCE (never reloaded) ----
    uint32_t Bf[2][4][8];
    #pragma unroll
    for (int tap = 0; tap < 2; tap++)
        #pragma unroll
        for (int ks = 0; ks < 4; ks++) {
            const uint32_t base = sb + W_OFF + tap * 9216 + (uint32_t)(ks * 32);
            LDMX4(&Bf[tap][ks][0], base + bb0);
            LDMX4(&Bf[tap][ks][4], base + bb1);
        }

    // ---- prologue: idx[0](tile0) -> gather E[0]; idx[1](tile0+NPERS) ----
    const int tile0 = blockIdx.x;
    if (tid < 160) {
        int b = tile0 * 2 + ib_b2, p = b & 15, nb = b >> 4;
        idx_s[0][tid] = ib_type + path_input[(((ib_a << 9) + nb) * 16 + p) * 5 + ib_t];
    }
    __syncthreads();
    #pragma unroll
    for (int g = 0; g < 5; g++) {
        int qq = (tid + g * 256) & 7;
        long long rbase = (long long)idx_s[0][grow[g]] * 16 + qq * 2;
        float4 va = __ldg(&tab4[rbase]);
        float4 vb = __ldg(&tab4[rbase + 1]);
        ulonglong2 hv;
        hv.x = pack4(va.x, va.y, va.z, va.w);
        hv.y = pack4(vb.x, vb.y, vb.z, vb.w);
        *reinterpret_cast<ulonglong2*>(smem + E0_OFF + goff[g]) = hv;
    }
    if (tid < 160 && tile0 + NPERS < 4096) {
        int b = (tile0 + NPERS) * 2 + ib_b2, p = b & 15, nb = b >> 4;
        idx_s[1][tid] = ib_type + path_input[(((ib_a << 9) + nb) * 16 + p) * 5 + ib_t];
    }
    __syncthreads();

    int n = 0;
    for (int tile = tile0; tile < 4096; tile += NPERS, n++) {
        const int  fr  = n & 1;
        const int  bk  = fr ^ 1;
        const bool nx  = tile + NPERS     < 4096;
        const bool nx2 = tile + 2 * NPERS < 4096;
        const uint32_t eF = fr ? E1_OFF : E0_OFF;
        const uint32_t eB = fr ? E0_OFF : E1_OFF;

        // ---- gather next tile directly into back E buffer ----
        if (nx) {
            #pragma unroll
            for (int g = 0; g < 5; g++) {
                int qq = (tid + g * 256) & 7;
                long long rbase = (long long)idx_s[bk][grow[g]] * 16 + qq * 2;
                float4 va = __ldg(&tab4[rbase]);
                float4 vb = __ldg(&tab4[rbase + 1]);
                ulonglong2 hv;
                hv.x = pack4(va.x, va.y, va.z, va.w);
                hv.y = pack4(vb.x, vb.y, vb.z, vb.w);
                *reinterpret_cast<ulonglong2*>(smem + eB + goff[g]) = hv;
            }
        }
        // ---- prefetch idx(tile + 2*NPERS) ----
        int ridx = 0;
        if (tid < 160 && nx2) {
            int b = (tile + 2 * NPERS) * 2 + ib_b2, p = b & 15, nb = b >> 4;
            ridx = ib_type + path_input[(((ib_a << 9) + nb) * 16 + p) * 5 + ib_t];
        }

        // ---- MMA on front E (B fragments already in registers) ----
        float d[2][4][4];
        #pragma unroll
        for (int mt = 0; mt < 2; mt++)
            #pragma unroll
            for (int nt = 0; nt < 4; nt++)
                #pragma unroll
                for (int r = 0; r < 4; r++) d[mt][nt][r] = 0.f;

        #pragma unroll
        for (int tap = 0; tap < 2; tap++) {
            const uint32_t aE0 = sb + eF + ab0 + tap * RSE;
            const uint32_t aE1 = sb + eF + ab1 + tap * RSE;
            #pragma unroll
            for (int ks = 0; ks < 4; ks++) {
                const uint32_t kb = (uint32_t)(ks * 32);
                uint32_t a0[4], a1[4];
                LDMX4(a0, aE0 + kb);
                LDMX4(a1, aE1 + kb);
                MMA(d[0][0], a0, Bf[tap][ks][0], Bf[tap][ks][1]);
                MMA(d[0][1], a0, Bf[tap][ks][2], Bf[tap][ks][3]);
                MMA(d[0][2], a0, Bf[tap][ks][4], Bf[tap][ks][5]);
                MMA(d[0][3], a0, Bf[tap][ks][6], Bf[tap][ks][7]);
                MMA(d[1][0], a1, Bf[tap][ks][0], Bf[tap][ks][1]);
                MMA(d[1][1], a1, Bf[tap][ks][2], Bf[tap][ks][3]);
                MMA(d[1][2], a1, Bf[tap][ks][4], Bf[tap][ks][5]);
                MMA(d[1][3], a1, Bf[tap][ks][6], Bf[tap][ks][7]);
            }
        }

        // ---- warp-local max over 32 m-rows -> red[fr][wid] ----
        #pragma unroll
        for (int nt = 0; nt < 4; nt++) {
            float v0 = fmaxf(fmaxf(d[0][nt][0], d[0][nt][2]),
                             fmaxf(d[1][nt][0], d[1][nt][2]));
            float v1 = fmaxf(fmaxf(d[0][nt][1], d[0][nt][3]),
                             fmaxf(d[1][nt][1], d[1][nt][3]));
            #pragma unroll
            for (int mask = 4; mask <= 16; mask <<= 1) {
                v0 = fmaxf(v0, __shfl_xor_sync(0xffffffffu, v0, mask));
                v1 = fmaxf(v1, __shfl_xor_sync(0xffffffffu, v1, mask));
            }
            if (lane < 4) {
                red[fr][wid][nt * 8 + lane * 2]     = v0;
                red[fr][wid][nt * 8 + lane * 2 + 1] = v1;
            }
        }
        if (tid < 160 && nx2) idx_s[fr][tid] = ridx;

        __syncthreads();

        // ---- store this tile's output ----
        if (tid < 128) {
            float m = fmaxf(red[fr][ow1][occ_], red[fr][ow1 + 1][occ_]);
            out[(long long)(tile * 2 + ob2) * 64 + oc] = m + bias;
        }
    }
}

extern "C" void kernel_launch(void* const* d_in, const int* in_sizes, int n_in,
                              void* d_out, int out_size) {
    const int*   path_input = (const int*)d_in[0];
    const int*   path_type  = (const int*)d_in[1];
    const float* tables     = (const float*)d_in[2];
    const float* conv_w     = (const float*)d_in[3];
    const float* conv_b     = (const float*)d_in[4];
    float* out = (float*)d_out;

    cudaFuncSetAttribute(path_emb_hmma,
                         cudaFuncAttributeMaxDynamicSharedMemorySize, SM_TOT);

    path_emb_hmma<<<NPERS, 256, SM_TOT>>>(path_input, path_type, tables,
                                          conv_w, conv_b, out);
}